// round 9
// baseline (speedup 1.0000x reference)
#include <cuda_runtime.h>

#define NN 384
#define DD 128
#define MARGIN_F 0.2f
#define TSM 16
#define TSN 64
#define NT 256
#define APAD 18
#define BPAD 66
#define MAXPOS 64
#define APB 4
#define NBLK (NN / APB)     // 96 triplet blocks -> single wave
#define NWARP_T 12

// Scratch (no allocations allowed)
__device__ float g_dot[NN * NN];
__device__ float g_r[NN];
__device__ float g_total;
__device__ float g_count;
__device__ unsigned int g_ctr;

// ---- GEMM: 16x64 tile, warp-row ownership (A reads are warp-uniform) ----
__global__ void __launch_bounds__(NT) gemm_k(const float* __restrict__ feat) {
    __shared__ float A2[DD][APAD];
    __shared__ float B2[DD][BPAD];

    const int t = threadIdx.x;
    const int w = t >> 5, lane = t & 31;
    const int j0 = blockIdx.x * TSN;
    const int i0 = blockIdx.y * TSM;
    const unsigned FULL = 0xFFFFFFFFu;

    // stage A (16 rows, k-major); norms folded in for bx==0
#pragma unroll
    for (int r = 0; r < 2; r++) {
        const int row = r * 8 + w;
        const float4 v = *reinterpret_cast<const float4*>(feat + (i0 + row) * DD + lane * 4);
        A2[4 * lane + 0][row] = v.x; A2[4 * lane + 1][row] = v.y;
        A2[4 * lane + 2][row] = v.z; A2[4 * lane + 3][row] = v.w;
        if (blockIdx.x == 0) {
            float ss = v.x * v.x + v.y * v.y + v.z * v.z + v.w * v.w;
#pragma unroll
            for (int off = 16; off > 0; off >>= 1)
                ss += __shfl_down_sync(FULL, ss, off);
            if (lane == 0) g_r[i0 + row] = ss;
        }
    }
    // stage B (64 rows, k-major)
#pragma unroll
    for (int r = 0; r < 8; r++) {
        const int row = r * 8 + w;
        const float4 v = *reinterpret_cast<const float4*>(feat + (j0 + row) * DD + lane * 4);
        B2[4 * lane + 0][row] = v.x; B2[4 * lane + 1][row] = v.y;
        B2[4 * lane + 2][row] = v.z; B2[4 * lane + 3][row] = v.w;
    }
    __syncthreads();

    float c00 = 0.f, c01 = 0.f, c10 = 0.f, c11 = 0.f;
#pragma unroll 8
    for (int k = 0; k < DD; k++) {
        const float2 a  = *reinterpret_cast<const float2*>(&A2[k][2 * w]);     // broadcast
        const float2 bb = *reinterpret_cast<const float2*>(&B2[k][2 * lane]);  // conflict-free
        c00 += a.x * bb.x; c01 += a.x * bb.y;
        c10 += a.y * bb.x; c11 += a.y * bb.y;
    }

    const int gi = i0 + 2 * w;
    const int gj = j0 + 2 * lane;
    *reinterpret_cast<float2*>(&g_dot[gi * NN + gj])       = make_float2(c00, c01);
    *reinterpret_cast<float2*>(&g_dot[(gi + 1) * NN + gj]) = make_float2(c10, c11);
}

// ---- triplet: 4 anchors per block, 96 blocks x 384 threads ----
__global__ void __launch_bounds__(NN) trip_k(const int* __restrict__ y,
                                             float* __restrict__ out) {
    const int t  = threadIdx.x;       // column j
    const int ab = blockIdx.x * APB;
    const int w = t >> 5, lane = t & 31;
    const unsigned FULL = 0xFFFFFFFFu;

    __shared__ int   yas[APB];
    __shared__ float pos_d[APB][MAXPOS];
    __shared__ int   wc[APB][NWARP_T];
    __shared__ int   wbase[APB][NWARP_T];
    __shared__ int   np_s[APB];
    __shared__ float red_f[NWARP_T];

    if (t < APB) yas[t] = y[ab + t];
    const int   yj = __ldg(&y[t]);
    const float rj = g_r[t];
    __syncthreads();

    float d2[APB];
    bool  isp[APB];
    unsigned pm[APB];
#pragma unroll
    for (int m = 0; m < APB; m++) {
        const int a = ab + m;
        const float dot = g_dot[a * NN + t];
        d2[m] = fmaxf(g_r[a] + rj - 2.0f * dot, 0.0f);
        isp[m] = (yj == yas[m]) && (t != a);
        pm[m] = __ballot_sync(FULL, isp[m]);
        if (lane == 0) wc[m][w] = __popc(pm[m]);
    }
    __syncthreads();
    if (t < APB) {
        int s = 0;
#pragma unroll
        for (int ww = 0; ww < NWARP_T; ww++) { wbase[t][ww] = s; s += wc[t][ww]; }
        np_s[t] = s;
    }
    __syncthreads();
#pragma unroll
    for (int m = 0; m < APB; m++) {
        if (isp[m]) {
            const int idx = wbase[m][w] + __popc(pm[m] & ((1u << lane) - 1u));
            pos_d[m][idx] = d2[m] + MARGIN_F;
        }
    }
    __syncthreads();

    float acc = 0.0f;
#pragma unroll
    for (int m = 0; m < APB; m++) {
        const int npm = np_s[m];
        if (yj != yas[m]) {
            const float dn = d2[m];
            for (int i = 0; i < npm; i++) {
                const float v = pos_d[m][i] - dn;
                acc += (v > 0.0f) ? v : 0.0f;
            }
        }
    }

    // block reduction + global accumulate + last-block finalize
#pragma unroll
    for (int off = 16; off > 0; off >>= 1)
        acc += __shfl_down_sync(FULL, acc, off);
    if (lane == 0) red_f[w] = acc;
    __syncthreads();
    if (w == 0) {
        float af = (lane < NWARP_T) ? red_f[lane] : 0.0f;
#pragma unroll
        for (int off = 8; off > 0; off >>= 1)
            af += __shfl_down_sync(FULL, af, off);
        if (lane == 0) {
            int cnt = 0;
#pragma unroll
            for (int m = 0; m < APB; m++)
                cnt += np_s[m] * (NN - 1 - np_s[m]);
            atomicAdd(&g_total, af);
            atomicAdd(&g_count, (float)cnt);
            __threadfence();
            const unsigned done = atomicAdd(&g_ctr, 1u);
            if (done == NBLK - 1) {
                const float tot = atomicAdd(&g_total, 0.0f);
                const float cn  = atomicAdd(&g_count, 0.0f);
                out[0] = tot / cn;
                g_total = 0.0f;
                g_count = 0.0f;
                g_ctr   = 0u;
            }
        }
    }
}

extern "C" void kernel_launch(void* const* d_in, const int* in_sizes, int n_in,
                              void* d_out, int out_size) {
    const float* feat = (const float*)d_in[0];
    // d_in[1] = logits (unused by the loss)
    const int*   yv   = (const int*)d_in[2];
    float* out = (float*)d_out;

    gemm_k<<<dim3(NN / TSN, NN / TSM), NT>>>(feat);
    trip_k<<<NBLK, NN>>>(yv, out);
}